// round 17
// baseline (speedup 1.0000x reference)
#include <cuda_runtime.h>
#include <cuda_fp16.h>
#include <cstdint>

typedef unsigned long long ull;

#define QSCALE 0.17677669529663687f

// fp16 B-fragment images, n ordering: [0,256)=Wq, [256,512)=Wkv.k, [512,768)=Wkv.v, [768,1024)=Wp
__device__ uint32_t g_wH[128][16][32][2];

// ---------------- helpers ----------------
__device__ __forceinline__ uint32_t hpack(float a, float b) {
    __half2 h = __floats2half2_rn(a, b);
    return *(uint32_t*)&h;
}
__device__ __forceinline__ void mma_f16(float* c, const uint32_t* a, const uint32_t* b) {
    asm volatile("mma.sync.aligned.m16n8k16.row.col.f32.f16.f16.f32 "
        "{%0,%1,%2,%3},{%4,%5,%6,%7},{%8,%9},{%0,%1,%2,%3};"
        : "+f"(c[0]), "+f"(c[1]), "+f"(c[2]), "+f"(c[3])
        : "r"(a[0]), "r"(a[1]), "r"(a[2]), "r"(a[3]), "r"(b[0]), "r"(b[1]));
}
#define BAR_PAIR(id) asm volatile("bar.sync %0, 64;" :: "r"(id) : "memory")

// ---------------- k0: weights -> fp16 B-fragment images ----------------
__global__ void k0_prep(const float* __restrict__ Wq, const float* __restrict__ Wkv,
                        const float* __restrict__ Wp) {
    int id = blockIdx.x * 512 + threadIdx.x;   // 131072
    int n = id >> 7, kp = id & 127;
    int k = kp * 2;
    float w0, w1;
    if (n < 256)      { w0 = Wq [k*256 + n];            w1 = Wq [(k+1)*256 + n]; }
    else if (n < 512) { w0 = Wkv[k*512 + (n-256)];      w1 = Wkv[(k+1)*512 + (n-256)]; }
    else if (n < 768) { w0 = Wkv[k*512 + 256 + (n-512)];w1 = Wkv[(k+1)*512 + 256 + (n-512)]; }
    else              { w0 = Wp [k*256 + (n-768)];      w1 = Wp [(k+1)*256 + (n-768)]; }
    int nt = n >> 3, kt = kp >> 3, kw = kp & 7;
    int lane = (n & 7) * 4 + (kw & 3), s = kw >> 2;
    g_wH[nt][kt][lane][s] = hpack(w0, w1);
}

// A-fragment store: fp32 (r, 4 k's) -> fp16 image, kt-XOR swizzled
__device__ __forceinline__ void stageA1h(uint32_t* A, int r, int k4, float4 v) {
    uint32_t hw[2] = { hpack(v.x, v.y), hpack(v.z, v.w) };
    int mt = r >> 4;
    #pragma unroll
    for (int w = 0; w < 2; ++w) {
        int kp = 2 * k4 + w;
        int kt = kp >> 3, kw = kp & 7;
        int lane = (((r & 7) << 2) | (kw & 3)) ^ (kt & 7);
        int s = ((r >> 3) & 1) | ((kw >> 2) << 1);
        A[(((mt * 16 + kt) * 32 + lane) << 2) | s] = hw[w];
    }
}
// A-fragment store of one half2 (row r, even col c2)
__device__ __forceinline__ void stageAw(uint32_t* A, int r, int c2, uint32_t hv) {
    int kp = c2 >> 1;
    int kt = kp >> 3, kw = kp & 7;
    int lane = (((r & 7) << 2) | (kw & 3)) ^ (kt & 7);
    int s = ((r >> 3) & 1) | ((kw >> 2) << 1);
    A[((((r >> 4) * 16 + kt) * 32 + lane) << 2) | s] = hv;
}

// warp GEMM: m32 x n32 tile, K-split (kk = 0/1 does kt 0..7 / 8..15)
__device__ __forceinline__ void gemm_ks(const uint32_t* __restrict__ sA,
                                        const uint32_t* __restrict__ sB,
                                        int kk, int mw, int nq, int lane,
                                        float acc[2][4][4]) {
    #pragma unroll
    for (int m = 0; m < 2; ++m)
        #pragma unroll
        for (int nt = 0; nt < 4; ++nt)
            #pragma unroll
            for (int i = 0; i < 4; ++i) acc[m][nt][i] = 0.f;
    #pragma unroll
    for (int k8 = 0; k8 < 8; ++k8) {
        int kt = kk * 8 + k8;
        int lx = lane ^ k8;                 // (kt & 7) == k8
        uint32_t a[2][4];
        #pragma unroll
        for (int m = 0; m < 2; ++m)
            *(uint4*)a[m] = *(const uint4*)(sA + ((((2 * mw + m) * 16 + kt) * 32 + lx) << 2));
        uint32_t b[4][2];
        #pragma unroll
        for (int nt = 0; nt < 4; ++nt)
            *(uint2*)b[nt] = *(const uint2*)(sB + ((((nq * 4 + nt) * 16 + kt) * 32 + lane) << 1));
        #pragma unroll
        for (int m = 0; m < 2; ++m)
            #pragma unroll
            for (int nt = 0; nt < 4; ++nt) mma_f16(acc[m][nt], a[m], b[nt]);
    }
}

// ---------------- fused kernel v4: all-MMA + K-split GEMM ----------------
// smem map (bytes):
//   [0, 32768)        sA   x A-frag image  -> reused as aoF
//   [32768, 98304)    sB   weight chunk
//   [98304, 132096)   qh   fp16 [64 rows][264 d]  (q, scaled)
//   [132096, 165888)  kh   fp16 [64 rows][264 d]
//   [165888, 202752)  vT   fp16 [256 d][72 rows]
//   [202752, 219136)  scr  fp32 K-split reduction scratch (8 pairs x 2KB)
#define SMEM_F 219136
#define QKS 264
#define VTS 72

__global__ void __launch_bounds__(512, 1)
k_fused(const float* __restrict__ x, const float* __restrict__ pos,
        const float* __restrict__ bp, float* __restrict__ out)
{
    extern __shared__ char smem[];
    uint32_t* sA = (uint32_t*)smem;               // also aoF
    uint32_t* sB = sA + 8192;
    __half*   qh = (__half*)(smem + 98304);
    __half*   kh = (__half*)(smem + 132096);
    __half*   vT = (__half*)(smem + 165888);
    float*    scr = (float*)(smem + 202752);

    const int t = threadIdx.x, win = blockIdx.x;
    const int b = win >> 10, nh = (win >> 5) & 31, nww = win & 31;
    const float* xb = x + (((size_t)(b * 256 + nh * 8) * 256 + nww * 8) << 8);
    const int w = t >> 5, lane = t & 31;
    const int gid = lane >> 2, tg = lane & 3;
    const int kk = w & 1, mw = (w >> 1) & 1, nq = w >> 2;
    const int pid = w >> 1;                       // pair id 0..7
    float* pscr = scr + pid * 512 + lane;

    // ---- phase 1: stage x -> sA ----
    #pragma unroll
    for (int rep = 0; rep < 8; ++rep) {
        int task = t + rep * 512;
        int r = task >> 6, k4 = task & 63;
        float4 v = *(const float4*)(xb + (size_t)(r >> 3) * 65536 + (r & 7) * 256 + k4 * 4);
        stageA1h(sA, r, k4, v);
    }

    // ---- phase 2: QKV GEMM (K-split), epilogue -> qh/kh/vT ----
    for (int ch = 0; ch < 6; ++ch) {
        __syncthreads();
        const uint4* srcB = (const uint4*)&g_wH[ch * 16][0][0][0];
        uint4* dB = (uint4*)sB;
        #pragma unroll
        for (int i = 0; i < 8; ++i) dB[t + i * 512] = srcB[t + i * 512];
        __syncthreads();
        float acc[2][4][4];
        gemm_ks(sA, sB, kk, mw, nq, lane, acc);
        #pragma unroll
        for (int r = 0; r < 2; ++r) {
            if (r == 1) BAR_PAIR(pid + 1);        // kk0 consumed round-0 scratch
            if (kk == 1) {
                #pragma unroll
                for (int i = 0; i < 16; ++i) pscr[i * 32] = acc[r][i >> 2][i & 3];
            }
            BAR_PAIR(pid + 1);
            if (kk == 0) {
                #pragma unroll
                for (int i = 0; i < 16; ++i) acc[r][i >> 2][i & 3] += pscr[i * 32];
                int row = (2 * mw + r) * 16 + gid;
                #pragma unroll
                for (int nt = 0; nt < 4; ++nt) {
                    int cc = (nq * 4 + nt) * 8 + tg * 2;
                    if (ch < 2) {            // q row-major, scaled
                        int d0 = ch * 128 + cc;
                        *(uint32_t*)(qh + row * QKS + d0) =
                            hpack(acc[r][nt][0] * QSCALE, acc[r][nt][1] * QSCALE);
                        *(uint32_t*)(qh + (row + 8) * QKS + d0) =
                            hpack(acc[r][nt][2] * QSCALE, acc[r][nt][3] * QSCALE);
                    } else if (ch < 4) {     // k row-major
                        int d0 = (ch - 2) * 128 + cc;
                        *(uint32_t*)(kh + row * QKS + d0) = hpack(acc[r][nt][0], acc[r][nt][1]);
                        *(uint32_t*)(kh + (row + 8) * QKS + d0) = hpack(acc[r][nt][2], acc[r][nt][3]);
                    } else {                 // v d-major
                        int d0 = (ch - 4) * 128 + cc;
                        vT[d0 * VTS + row]           = __float2half_rn(acc[r][nt][0]);
                        vT[(d0 + 1) * VTS + row]     = __float2half_rn(acc[r][nt][1]);
                        vT[d0 * VTS + row + 8]       = __float2half_rn(acc[r][nt][2]);
                        vT[(d0 + 1) * VTS + row + 8] = __float2half_rn(acc[r][nt][3]);
                    }
                }
            }
        }
    }
    __syncthreads();

    // ---- phase 3: attention, fully on tensor cores ----
    #pragma unroll
    for (int it = 0; it < 2; ++it) {
        int task = w + 16 * it;
        int h = task >> 2, rb = task & 3;
        int r0 = rb * 16;

        uint32_t qa[2][4];
        const __half* qrow = qh + (r0 + gid) * QKS + h * 32 + tg * 2;
        #pragma unroll
        for (int ks = 0; ks < 2; ++ks) {
            qa[ks][0] = *(const uint32_t*)(qrow + ks * 16);
            qa[ks][1] = *(const uint32_t*)(qrow + 8 * QKS + ks * 16);
            qa[ks][2] = *(const uint32_t*)(qrow + ks * 16 + 8);
            qa[ks][3] = *(const uint32_t*)(qrow + 8 * QKS + ks * 16 + 8);
        }

        float ss[8][4];
        #pragma unroll
        for (int nt = 0; nt < 8; ++nt) {
            ss[nt][0] = ss[nt][1] = ss[nt][2] = ss[nt][3] = 0.f;
            const __half* krow = kh + (nt * 8 + gid) * QKS + h * 32 + tg * 2;
            #pragma unroll
            for (int ks = 0; ks < 2; ++ks) {
                uint32_t kb[2] = { *(const uint32_t*)(krow + ks * 16),
                                   *(const uint32_t*)(krow + ks * 16 + 8) };
                mma_f16(ss[nt], qa[ks], kb);
            }
        }

        const float* pb = pos + h * 4096 + (r0 + gid) * 64 + tg * 2;
        #pragma unroll
        for (int nt = 0; nt < 8; ++nt) {
            float2 p0 = __ldg((const float2*)(pb + nt * 8));
            float2 p1 = __ldg((const float2*)(pb + 8 * 64 + nt * 8));
            ss[nt][0] += p0.x; ss[nt][1] += p0.y;
            ss[nt][2] += p1.x; ss[nt][3] += p1.y;
        }

        float mA = ss[0][0], mB = ss[0][2];
        #pragma unroll
        for (int nt = 0; nt < 8; ++nt) {
            mA = fmaxf(mA, fmaxf(ss[nt][0], ss[nt][1]));
            mB = fmaxf(mB, fmaxf(ss[nt][2], ss[nt][3]));
        }
        #pragma unroll
        for (int o = 1; o < 4; o <<= 1) {
            mA = fmaxf(mA, __shfl_xor_sync(0xffffffffu, mA, o));
            mB = fmaxf(mB, __shfl_xor_sync(0xffffffffu, mB, o));
        }
        float sA_ = 0.f, sB_ = 0.f;
        #pragma unroll
        for (int nt = 0; nt < 8; ++nt) {
            ss[nt][0] = __expf(ss[nt][0] - mA); sA_ += ss[nt][0];
            ss[nt][1] = __expf(ss[nt][1] - mA); sA_ += ss[nt][1];
            ss[nt][2] = __expf(ss[nt][2] - mB); sB_ += ss[nt][2];
            ss[nt][3] = __expf(ss[nt][3] - mB); sB_ += ss[nt][3];
        }
        #pragma unroll
        for (int o = 1; o < 4; o <<= 1) {
            sA_ += __shfl_xor_sync(0xffffffffu, sA_, o);
            sB_ += __shfl_xor_sync(0xffffffffu, sB_, o);
        }
        float invA = 1.f / sA_, invB = 1.f / sB_;

        uint32_t pa[4][4];
        #pragma unroll
        for (int kkp = 0; kkp < 4; ++kkp) {
            pa[kkp][0] = hpack(ss[2*kkp][0]   * invA, ss[2*kkp][1]   * invA);
            pa[kkp][1] = hpack(ss[2*kkp][2]   * invB, ss[2*kkp][3]   * invB);
            pa[kkp][2] = hpack(ss[2*kkp+1][0] * invA, ss[2*kkp+1][1] * invA);
            pa[kkp][3] = hpack(ss[2*kkp+1][2] * invB, ss[2*kkp+1][3] * invB);
        }

        float oo[4][4];
        #pragma unroll
        for (int dt = 0; dt < 4; ++dt)
            oo[dt][0] = oo[dt][1] = oo[dt][2] = oo[dt][3] = 0.f;
        #pragma unroll
        for (int kkp = 0; kkp < 4; ++kkp) {
            #pragma unroll
            for (int dt = 0; dt < 4; ++dt) {
                const __half* vrow = vT + (h * 32 + dt * 8 + gid) * VTS + kkp * 16 + tg * 2;
                uint32_t vb[2] = { *(const uint32_t*)(vrow),
                                   *(const uint32_t*)(vrow + 8) };
                mma_f16(oo[dt], pa[kkp], vb);
            }
        }

        #pragma unroll
        for (int dt = 0; dt < 4; ++dt) {
            int d0 = h * 32 + dt * 8 + tg * 2;
            stageAw(sA, r0 + gid,     d0, hpack(oo[dt][0], oo[dt][1]));
            stageAw(sA, r0 + gid + 8, d0, hpack(oo[dt][2], oo[dt][3]));
        }
    }
    __syncthreads();

    // ---- phase 4: projection GEMM (K-split) + bias + un-window ----
    float* obase = out + (((size_t)(b * 256 + nh * 8) * 256 + nww * 8) << 8);
    for (int ch = 0; ch < 2; ++ch) {
        __syncthreads();
        const uint4* srcB = (const uint4*)&g_wH[96 + ch * 16][0][0][0];
        uint4* dB = (uint4*)sB;
        #pragma unroll
        for (int i = 0; i < 8; ++i) dB[t + i * 512] = srcB[t + i * 512];
        __syncthreads();
        float acc[2][4][4];
        gemm_ks(sA, sB, kk, mw, nq, lane, acc);
        #pragma unroll
        for (int r = 0; r < 2; ++r) {
            if (r == 1) BAR_PAIR(pid + 1);
            if (kk == 1) {
                #pragma unroll
                for (int i = 0; i < 16; ++i) pscr[i * 32] = acc[r][i >> 2][i & 3];
            }
            BAR_PAIR(pid + 1);
            if (kk == 0) {
                #pragma unroll
                for (int i = 0; i < 16; ++i) acc[r][i >> 2][i & 3] += pscr[i * 32];
                int row = (2 * mw + r) * 16 + gid;
                #pragma unroll
                for (int nt = 0; nt < 4; ++nt) {
                    int c = ch * 128 + (nq * 4 + nt) * 8 + tg * 2;
                    float2 bias = *(const float2*)(bp + c);
                    int r0w = row, r1w = row + 8;
                    *(float2*)(obase + (r0w >> 3) * 65536 + (r0w & 7) * 256 + c) =
                        make_float2(acc[r][nt][0] + bias.x, acc[r][nt][1] + bias.y);
                    *(float2*)(obase + (r1w >> 3) * 65536 + (r1w & 7) * 256 + c) =
                        make_float2(acc[r][nt][2] + bias.x, acc[r][nt][3] + bias.y);
                }
            }
        }
    }
}

extern "C" void kernel_launch(void* const* d_in, const int* in_sizes, int n_in,
                              void* d_out, int out_size)
{
    const float* x   = (const float*)d_in[0];
    const float* Wq  = (const float*)d_in[1];
    const float* Wkv = (const float*)d_in[2];
    const float* pos = (const float*)d_in[3];
    const float* Wp  = (const float*)d_in[4];
    const float* bp  = (const float*)d_in[5];
    float* out = (float*)d_out;

    cudaFuncSetAttribute(k_fused, cudaFuncAttributeMaxDynamicSharedMemorySize, SMEM_F);

    k0_prep<<<256, 512>>>(Wq, Wkv, Wp);
    k_fused<<<4096, 512, SMEM_F>>>(x, pos, bp, out);
}